// round 14
// baseline (speedup 1.0000x reference)
#include <cuda_runtime.h>
#include <cstdint>
#include <cstddef>

// ---------------------------------------------------------------------------
// DataDependentRBFKernel — software-pipelined two-stream graph.
//   Rows chunked 4 x 2048. sigma chunk c (capture stream) -> event ->
//   rbf chunk c (second stream). HW co-schedules sigma chunk c+1 with
//   rbf chunk c: sigma is FMA/LDS-bound, rbf is MUFU/L2-store-bound.
//   sigma: proven R4 core (32 rows/256-thr block, e+w1 smem-staged).
//   rbf:   proven R6 core (8 rows x 1024 z, 4 pts/thread, 40 regs).
// ---------------------------------------------------------------------------

#define EDIM 256
#define H1DIM 32
#define H2DIM 16
#define SROWS 32
#define NCHUNK 4
#define CROWS (8192 / NCHUNK)     // 2048 rows per chunk

__device__ float4 g_coef[8192];   // per-row (sc, c0, c1, cc)

__device__ __forceinline__ float ex2_approx(float x) {
    float y;
    asm("ex2.approx.f32 %0, %1;" : "=f"(y) : "f"(x));
    return y;
}
__device__ __forceinline__ float gelu_exact(float x) {
    return 0.5f * x * (1.0f + erff(x * 0.70710678118654752440f));
}

// smem (floats): e_s[32*256] | w1_s[256*32] | w2_s[32*16] | h1_s[32*32] | h2_s[32*16]
#define SIG_SMEM_FLOATS (SROWS*EDIM + EDIM*H1DIM + H1DIM*H2DIM + SROWS*H1DIM + SROWS*H2DIM)

// -------------------- sigma MLP: 32 rows per 256-thread block --------------
__global__ __launch_bounds__(256)
void sigma_kernel(const float* __restrict__ emb, const float* __restrict__ mu,
                  const float* __restrict__ w1, const float* __restrict__ b1,
                  const float* __restrict__ w2, const float* __restrict__ b2,
                  const float* __restrict__ w3, const float* __restrict__ b3,
                  int rowoff)
{
    extern __shared__ float smem[];
    float* e_s  = smem;                        // 8192
    float* w1_s = e_s + SROWS * EDIM;          // 8192
    float* w2_s = w1_s + EDIM * H1DIM;         // 512
    float* h1_s = w2_s + H1DIM * H2DIM;        // 1024
    float* h2_s = h1_s + SROWS * H1DIM;        // 512

    const int tid = threadIdx.x;
    const int rowbase = rowoff + blockIdx.x * SROWS;

    // ---- cooperative staging (float4, coalesced) ----
    {
        const float4* e4 = reinterpret_cast<const float4*>(emb + (size_t)rowbase * EDIM);
        float4* es4 = reinterpret_cast<float4*>(e_s);
        #pragma unroll
        for (int i = 0; i < (SROWS * EDIM / 4) / 256; ++i)   // 8
            es4[tid + i * 256] = e4[tid + i * 256];

        const float4* w14 = reinterpret_cast<const float4*>(w1);
        float4* w1s4 = reinterpret_cast<float4*>(w1_s);
        #pragma unroll
        for (int i = 0; i < (EDIM * H1DIM / 4) / 256; ++i)   // 8
            w1s4[tid + i * 256] = w14[tid + i * 256];

        if (tid < (H1DIM * H2DIM / 4))
            reinterpret_cast<float4*>(w2_s)[tid] =
                reinterpret_cast<const float4*>(w2)[tid];
    }
    __syncthreads();

    // ---- layer 1: warp w -> rows 4w..4w+3, lane = unit j ----
    {
        const int j = tid & 31;
        const int w = tid >> 5;
        const float* e0 = e_s + (w * 4) * EDIM;

        float acc0, acc1, acc2, acc3;
        acc0 = acc1 = acc2 = acc3 = __ldg(&b1[j]);

        #pragma unroll 8
        for (int k = 0; k < EDIM; k += 4) {
            const float wv0 = w1_s[(k + 0) * H1DIM + j];
            const float wv1 = w1_s[(k + 1) * H1DIM + j];
            const float wv2 = w1_s[(k + 2) * H1DIM + j];
            const float wv3 = w1_s[(k + 3) * H1DIM + j];
            float4 e;
            e = *reinterpret_cast<const float4*>(e0 + 0 * EDIM + k);
            acc0 = fmaf(e.x, wv0, acc0); acc0 = fmaf(e.y, wv1, acc0);
            acc0 = fmaf(e.z, wv2, acc0); acc0 = fmaf(e.w, wv3, acc0);
            e = *reinterpret_cast<const float4*>(e0 + 1 * EDIM + k);
            acc1 = fmaf(e.x, wv0, acc1); acc1 = fmaf(e.y, wv1, acc1);
            acc1 = fmaf(e.z, wv2, acc1); acc1 = fmaf(e.w, wv3, acc1);
            e = *reinterpret_cast<const float4*>(e0 + 2 * EDIM + k);
            acc2 = fmaf(e.x, wv0, acc2); acc2 = fmaf(e.y, wv1, acc2);
            acc2 = fmaf(e.z, wv2, acc2); acc2 = fmaf(e.w, wv3, acc2);
            e = *reinterpret_cast<const float4*>(e0 + 3 * EDIM + k);
            acc3 = fmaf(e.x, wv0, acc3); acc3 = fmaf(e.y, wv1, acc3);
            acc3 = fmaf(e.z, wv2, acc3); acc3 = fmaf(e.w, wv3, acc3);
        }
        h1_s[(w * 4 + 0) * H1DIM + j] = gelu_exact(acc0);
        h1_s[(w * 4 + 1) * H1DIM + j] = gelu_exact(acc1);
        h1_s[(w * 4 + 2) * H1DIM + j] = gelu_exact(acc2);
        h1_s[(w * 4 + 3) * H1DIM + j] = gelu_exact(acc3);
    }
    __syncthreads();

    // ---- layer 2: 32 rows x 16 units = 512 items, 2 per thread ----
    {
        #pragma unroll
        for (int it = 0; it < 2; ++it) {
            const int item = tid + it * 256;
            const int r = item >> 4;
            const int m = item & 15;
            float acc = __ldg(&b2[m]);
            #pragma unroll
            for (int j = 0; j < H1DIM; ++j)
                acc = fmaf(h1_s[r * H1DIM + j], w2_s[j * H2DIM + m], acc);
            h2_s[r * H2DIM + m] = gelu_exact(acc);
        }
    }
    __syncthreads();

    // ---- layer 3 + sigmoid + affine + fold mu -> g_coef ----
    if (tid < SROWS) {
        float s = __ldg(&b3[0]);
        #pragma unroll
        for (int m = 0; m < H2DIM; ++m)
            s = fmaf(h2_s[tid * H2DIM + m], __ldg(&w3[m]), s);
        const float sig = 1.0f / (1.0f + expf(-s));
        const float sigma = 0.1f + 9.9f * sig;
        const float sc = -1.44269504088896340736f / (2.0f * sigma * sigma);
        const float2 muv = reinterpret_cast<const float2*>(mu)[rowbase + tid];
        const float c0 = -2.0f * sc * muv.x;
        const float c1 = -2.0f * sc * muv.y;
        const float cc = sc * (muv.x * muv.x + muv.y * muv.y);
        g_coef[rowbase + tid] = make_float4(sc, c0, c1, cc);
    }
}

// -------------------- RBF sweep: 8 rows x 1024 z per 256-thread block ------
__global__ __launch_bounds__(256)
void rbf_kernel(const float* __restrict__ z, float* __restrict__ out, int M,
                int rowoff)
{
    constexpr int TILE_R = 8;

    const int t = threadIdx.x;
    const int zb = blockIdx.x * 1024 + t * 4;
    const int rowbase = rowoff + blockIdx.y * TILE_R;

    float z0[4], z1[4], r2[4];
    {
        const float4* z4 = reinterpret_cast<const float4*>(z);
        #pragma unroll
        for (int i = 0; i < 2; ++i) {
            float4 v = __ldg(&z4[(size_t)(blockIdx.x * 512) + (size_t)t * 2 + i]);
            z0[2 * i]     = v.x;  z1[2 * i]     = v.y;
            z0[2 * i + 1] = v.z;  z1[2 * i + 1] = v.w;
        }
        #pragma unroll
        for (int i = 0; i < 4; ++i)
            r2[i] = z0[i] * z0[i] + z1[i] * z1[i];
    }

    float* optr = out + (size_t)rowbase * (size_t)M + (size_t)zb;

    #pragma unroll
    for (int r = 0; r < TILE_R; ++r) {
        const float4 c = __ldg(&g_coef[rowbase + r]);   // uniform -> broadcast
        float o[4];
        #pragma unroll
        for (int i = 0; i < 4; ++i) {
            float a = fmaf(c.x, r2[i], fmaf(c.y, z0[i], fmaf(c.z, z1[i], c.w)));
            o[i] = ex2_approx(a);
        }
        *reinterpret_cast<float4*>(optr) = make_float4(o[0], o[1], o[2], o[3]);
        optr += M;
    }
}

// ---------------------------------------------------------------------------
extern "C" void kernel_launch(void* const* d_in, const int* in_sizes, int n_in,
                              void* d_out, int out_size)
{
    const float* z   = (const float*)d_in[0];   // [M, 2]
    const float* mu  = (const float*)d_in[1];   // [B, N, 2]
    const float* emb = (const float*)d_in[2];   // [B, N, 256]
    const float* w1  = (const float*)d_in[3];   // [256, 32]
    const float* b1  = (const float*)d_in[4];   // [32]
    const float* w2  = (const float*)d_in[5];   // [32, 16]
    const float* b2  = (const float*)d_in[6];   // [16]
    const float* w3  = (const float*)d_in[7];   // [16, 1]
    const float* b3  = (const float*)d_in[8];   // [1]
    float* out = (float*)d_out;

    const int M = in_sizes[0] / 2;    // 2048

    // static stream/events: created on the first (non-captured) call.
    static cudaStream_t s2 = nullptr;
    static cudaEvent_t  ev[NCHUNK];
    static cudaEvent_t  evj;
    static int smem_bytes = 0;
    if (!s2) {
        cudaStreamCreateWithFlags(&s2, cudaStreamNonBlocking);
        for (int c = 0; c < NCHUNK; ++c)
            cudaEventCreateWithFlags(&ev[c], cudaEventDisableTiming);
        cudaEventCreateWithFlags(&evj, cudaEventDisableTiming);
        smem_bytes = SIG_SMEM_FLOATS * sizeof(float);
        cudaFuncSetAttribute(sigma_kernel,
                             cudaFuncAttributeMaxDynamicSharedMemorySize,
                             smem_bytes);
    }

    // sigma chunks in the capture (default) stream, each signals an event
    for (int c = 0; c < NCHUNK; ++c) {
        sigma_kernel<<<CROWS / SROWS, 256, smem_bytes>>>(
            emb, mu, w1, b1, w2, b2, w3, b3, c * CROWS);
        cudaEventRecord(ev[c], 0);
    }

    // rbf chunks in the second stream, each gated on its sigma chunk
    for (int c = 0; c < NCHUNK; ++c) {
        cudaStreamWaitEvent(s2, ev[c], 0);
        dim3 grid(M / 1024, CROWS / 8);
        rbf_kernel<<<grid, 256, 0, s2>>>(z, out, M, c * CROWS);
    }

    // join second stream back into the capture stream
    cudaEventRecord(evj, s2);
    cudaStreamWaitEvent(0, evj, 0);
}

// round 15
// speedup vs baseline: 1.7246x; 1.7246x over previous
#include <cuda_runtime.h>
#include <cstdint>
#include <cstddef>

// ---------------------------------------------------------------------------
// DataDependentRBFKernel — two kernels.
//   sigma_kernel: R4 shape (32 rows / 256-thread block, e+w1 smem, grid 256)
//                 with an explicitly software-pipelined layer-1 loop:
//                 next k-group's 8 smem loads issue before current group's
//                 16 FMAs, hiding the 29-cyc LDS latency that the profile
//                 showed dominating (regs=36 -> no lookahead).
//   rbf_kernel:   proven: 8 rows x 1024 z, 4 pts/thread, grid (2,1024).
// ---------------------------------------------------------------------------

#define EDIM 256
#define H1DIM 32
#define H2DIM 16
#define SROWS 32

__device__ float4 g_coef[8192];   // per-row (sc, c0, c1, cc)

__device__ __forceinline__ float ex2_approx(float x) {
    float y;
    asm("ex2.approx.f32 %0, %1;" : "=f"(y) : "f"(x));
    return y;
}
__device__ __forceinline__ float gelu_exact(float x) {
    return 0.5f * x * (1.0f + erff(x * 0.70710678118654752440f));
}

// smem (floats): e_s[32*256] | w1_s[256*32] | w2_s[32*16] | h1_s[32*32] | h2_s[32*16]
#define SIG_SMEM_FLOATS (SROWS*EDIM + EDIM*H1DIM + H1DIM*H2DIM + SROWS*H1DIM + SROWS*H2DIM)

// -------------------- sigma MLP: 32 rows per 256-thread block --------------
__global__ __launch_bounds__(256)
void sigma_kernel(const float* __restrict__ emb, const float* __restrict__ mu,
                  const float* __restrict__ w1, const float* __restrict__ b1,
                  const float* __restrict__ w2, const float* __restrict__ b2,
                  const float* __restrict__ w3, const float* __restrict__ b3)
{
    extern __shared__ float smem[];
    float* e_s  = smem;                        // 8192
    float* w1_s = e_s + SROWS * EDIM;          // 8192
    float* w2_s = w1_s + EDIM * H1DIM;         // 512
    float* h1_s = w2_s + H1DIM * H2DIM;        // 1024
    float* h2_s = h1_s + SROWS * H1DIM;        // 512

    const int tid = threadIdx.x;
    const int rowbase = blockIdx.x * SROWS;

    // ---- cooperative staging (float4, coalesced) ----
    {
        const float4* e4 = reinterpret_cast<const float4*>(emb + (size_t)rowbase * EDIM);
        float4* es4 = reinterpret_cast<float4*>(e_s);
        #pragma unroll
        for (int i = 0; i < (SROWS * EDIM / 4) / 256; ++i)   // 8
            es4[tid + i * 256] = e4[tid + i * 256];

        const float4* w14 = reinterpret_cast<const float4*>(w1);
        float4* w1s4 = reinterpret_cast<float4*>(w1_s);
        #pragma unroll
        for (int i = 0; i < (EDIM * H1DIM / 4) / 256; ++i)   // 8
            w1s4[tid + i * 256] = w14[tid + i * 256];

        if (tid < (H1DIM * H2DIM / 4))
            reinterpret_cast<float4*>(w2_s)[tid] =
                reinterpret_cast<const float4*>(w2)[tid];
    }
    __syncthreads();

    // ---- layer 1 (software-pipelined): warp w -> rows 4w..4w+3 ----
    {
        const int j = tid & 31;
        const int w = tid >> 5;
        const float* e0 = e_s + (w * 4) * EDIM;

        float acc0, acc1, acc2, acc3;
        acc0 = acc1 = acc2 = acc3 = __ldg(&b1[j]);

        // prologue: load k-group 0
        float  wv0 = w1_s[0 * H1DIM + j];
        float  wv1 = w1_s[1 * H1DIM + j];
        float  wv2 = w1_s[2 * H1DIM + j];
        float  wv3 = w1_s[3 * H1DIM + j];
        float4 ea = *reinterpret_cast<const float4*>(e0 + 0 * EDIM);
        float4 eb = *reinterpret_cast<const float4*>(e0 + 1 * EDIM);
        float4 ec = *reinterpret_cast<const float4*>(e0 + 2 * EDIM);
        float4 ed = *reinterpret_cast<const float4*>(e0 + 3 * EDIM);

        #pragma unroll 8
        for (int k = 0; k < EDIM - 4; k += 4) {
            // stash current group
            const float  u0 = wv0, u1 = wv1, u2 = wv2, u3 = wv3;
            const float4 a = ea, b = eb, c = ec, d = ed;
            // issue next group's loads BEFORE consuming current
            const int kn = k + 4;
            wv0 = w1_s[(kn + 0) * H1DIM + j];
            wv1 = w1_s[(kn + 1) * H1DIM + j];
            wv2 = w1_s[(kn + 2) * H1DIM + j];
            wv3 = w1_s[(kn + 3) * H1DIM + j];
            ea = *reinterpret_cast<const float4*>(e0 + 0 * EDIM + kn);
            eb = *reinterpret_cast<const float4*>(e0 + 1 * EDIM + kn);
            ec = *reinterpret_cast<const float4*>(e0 + 2 * EDIM + kn);
            ed = *reinterpret_cast<const float4*>(e0 + 3 * EDIM + kn);
            // consume stashed group
            acc0 = fmaf(a.x, u0, acc0); acc0 = fmaf(a.y, u1, acc0);
            acc0 = fmaf(a.z, u2, acc0); acc0 = fmaf(a.w, u3, acc0);
            acc1 = fmaf(b.x, u0, acc1); acc1 = fmaf(b.y, u1, acc1);
            acc1 = fmaf(b.z, u2, acc1); acc1 = fmaf(b.w, u3, acc1);
            acc2 = fmaf(c.x, u0, acc2); acc2 = fmaf(c.y, u1, acc2);
            acc2 = fmaf(c.z, u2, acc2); acc2 = fmaf(c.w, u3, acc2);
            acc3 = fmaf(d.x, u0, acc3); acc3 = fmaf(d.y, u1, acc3);
            acc3 = fmaf(d.z, u2, acc3); acc3 = fmaf(d.w, u3, acc3);
        }
        // epilogue: consume last group
        acc0 = fmaf(ea.x, wv0, acc0); acc0 = fmaf(ea.y, wv1, acc0);
        acc0 = fmaf(ea.z, wv2, acc0); acc0 = fmaf(ea.w, wv3, acc0);
        acc1 = fmaf(eb.x, wv0, acc1); acc1 = fmaf(eb.y, wv1, acc1);
        acc1 = fmaf(eb.z, wv2, acc1); acc1 = fmaf(eb.w, wv3, acc1);
        acc2 = fmaf(ec.x, wv0, acc2); acc2 = fmaf(ec.y, wv1, acc2);
        acc2 = fmaf(ec.z, wv2, acc2); acc2 = fmaf(ec.w, wv3, acc2);
        acc3 = fmaf(ed.x, wv0, acc3); acc3 = fmaf(ed.y, wv1, acc3);
        acc3 = fmaf(ed.z, wv2, acc3); acc3 = fmaf(ed.w, wv3, acc3);

        h1_s[(w * 4 + 0) * H1DIM + j] = gelu_exact(acc0);
        h1_s[(w * 4 + 1) * H1DIM + j] = gelu_exact(acc1);
        h1_s[(w * 4 + 2) * H1DIM + j] = gelu_exact(acc2);
        h1_s[(w * 4 + 3) * H1DIM + j] = gelu_exact(acc3);
    }
    __syncthreads();

    // ---- layer 2: 32 rows x 16 units = 512 items, 2 per thread ----
    {
        #pragma unroll
        for (int it = 0; it < 2; ++it) {
            const int item = tid + it * 256;
            const int r = item >> 4;
            const int m = item & 15;
            float acc = __ldg(&b2[m]);
            #pragma unroll
            for (int j = 0; j < H1DIM; ++j)
                acc = fmaf(h1_s[r * H1DIM + j], w2_s[j * H2DIM + m], acc);
            h2_s[r * H2DIM + m] = gelu_exact(acc);
        }
    }
    __syncthreads();

    // ---- layer 3 + sigmoid + affine + fold mu -> g_coef ----
    if (tid < SROWS) {
        float s = __ldg(&b3[0]);
        #pragma unroll
        for (int m = 0; m < H2DIM; ++m)
            s = fmaf(h2_s[tid * H2DIM + m], __ldg(&w3[m]), s);
        const float sig = 1.0f / (1.0f + expf(-s));
        const float sigma = 0.1f + 9.9f * sig;
        const float sc = -1.44269504088896340736f / (2.0f * sigma * sigma);
        const float2 muv = reinterpret_cast<const float2*>(mu)[rowbase + tid];
        const float c0 = -2.0f * sc * muv.x;
        const float c1 = -2.0f * sc * muv.y;
        const float cc = sc * (muv.x * muv.x + muv.y * muv.y);
        g_coef[rowbase + tid] = make_float4(sc, c0, c1, cc);
    }
}

// -------------------- RBF sweep: 8 rows x 1024 z per 256-thread block ------
__global__ __launch_bounds__(256)
void rbf_kernel(const float* __restrict__ z, float* __restrict__ out, int M)
{
    constexpr int TILE_R = 8;

    const int t = threadIdx.x;
    const int zb = blockIdx.x * 1024 + t * 4;
    const int rowbase = blockIdx.y * TILE_R;

    float z0[4], z1[4], r2[4];
    {
        const float4* z4 = reinterpret_cast<const float4*>(z);
        #pragma unroll
        for (int i = 0; i < 2; ++i) {
            float4 v = __ldg(&z4[(size_t)(blockIdx.x * 512) + (size_t)t * 2 + i]);
            z0[2 * i]     = v.x;  z1[2 * i]     = v.y;
            z0[2 * i + 1] = v.z;  z1[2 * i + 1] = v.w;
        }
        #pragma unroll
        for (int i = 0; i < 4; ++i)
            r2[i] = z0[i] * z0[i] + z1[i] * z1[i];
    }

    float* optr = out + (size_t)rowbase * (size_t)M + (size_t)zb;

    #pragma unroll
    for (int r = 0; r < TILE_R; ++r) {
        const float4 c = __ldg(&g_coef[rowbase + r]);   // uniform -> broadcast
        float o[4];
        #pragma unroll
        for (int i = 0; i < 4; ++i) {
            float a = fmaf(c.x, r2[i], fmaf(c.y, z0[i], fmaf(c.z, z1[i], c.w)));
            o[i] = ex2_approx(a);
        }
        *reinterpret_cast<float4*>(optr) = make_float4(o[0], o[1], o[2], o[3]);
        optr += M;
    }
}

// ---------------------------------------------------------------------------
extern "C" void kernel_launch(void* const* d_in, const int* in_sizes, int n_in,
                              void* d_out, int out_size)
{
    const float* z   = (const float*)d_in[0];   // [M, 2]
    const float* mu  = (const float*)d_in[1];   // [B, N, 2]
    const float* emb = (const float*)d_in[2];   // [B, N, 256]
    const float* w1  = (const float*)d_in[3];   // [256, 32]
    const float* b1  = (const float*)d_in[4];   // [32]
    const float* w2  = (const float*)d_in[5];   // [32, 16]
    const float* b2  = (const float*)d_in[6];   // [16]
    const float* w3  = (const float*)d_in[7];   // [16, 1]
    const float* b3  = (const float*)d_in[8];   // [1]
    float* out = (float*)d_out;

    const int M  = in_sizes[0] / 2;   // 2048
    const int BN = in_sizes[1] / 2;   // 8192

    const int smem_bytes = SIG_SMEM_FLOATS * sizeof(float);
    static bool attr_set = false;
    if (!attr_set) {
        cudaFuncSetAttribute(sigma_kernel,
                             cudaFuncAttributeMaxDynamicSharedMemorySize,
                             smem_bytes);
        attr_set = true;
    }

    sigma_kernel<<<BN / SROWS, 256, smem_bytes>>>(emb, mu, w1, b1, w2, b2, w3, b3);

    dim3 grid(M / 1024, BN / 8);
    rbf_kernel<<<grid, 256>>>(z, out, M);
}